// round 6
// baseline (speedup 1.0000x reference)
#include <cuda_runtime.h>
#include <math.h>

#define ESL   4096
#define BATCH 64
#define EHS   256
#define NBLK  592              // 148 SMs * 4 -> exactly 4 blocks per SM
#define NWARP (NBLK * 8)       // 4736 = 64 * 74
#define WPB   74               // warps per batch
#define TASK_ROWS 8
#define NTASK (ESL / TASK_ROWS)  // 512 tasks per batch

// per-warp partials: [j (0..73)][b][EHS] and [j][b]
__device__ float g_pc[WPB * BATCH * EHS];
__device__ float g_pz[WPB * BATCH];

__device__ __forceinline__ float dot4(float4 a, float4 b) {
    return a.x*b.x + a.y*b.y + a.z*b.z + a.w*b.w;
}

__global__ __launch_bounds__(256)
void attn_pass1(const float* __restrict__ si,   // (1,64,256)
                const float* __restrict__ h,    // (4096,64,256)
                const float* __restrict__ W,    // (1,512) [Wd|We]
                const float* __restrict__ bias) // (1,)
{
    const int g    = blockIdx.x * 8 + (threadIdx.x >> 5);
    const int lane = threadIdx.x & 31;
    const int b    = g & 63;         // 4736 warps -> each b exactly 74 times
    const int j    = g >> 6;         // 0..73

    // We slices for this lane (channels 4*lane.. and 4*(lane+32)..)
    const float4* We4 = (const float4*)(W + EHS);
    const float4 we0 = We4[lane];
    const float4 we1 = We4[lane + 32];

    // d = dot(si[b], Wd) + bias (redundant per warp; negligible)
    const float4* Wd4 = (const float4*)W;
    const float4* si4 = (const float4*)(si + b * EHS);
    float4 a0 = si4[lane], a1 = si4[lane + 32];
    float4 w0 = Wd4[lane], w1 = Wd4[lane + 32];
    float d = dot4(a0, w0) + dot4(a1, w1);
    #pragma unroll
    for (int o = 16; o; o >>= 1) d += __shfl_xor_sync(0xFFFFFFFFu, d, o);
    d += bias[0];

    const size_t row_stride = (size_t)BATCH * EHS;   // floats between s and s+1

    float Z = 0.0f;
    float4 c0 = make_float4(0.f, 0.f, 0.f, 0.f);
    float4 c1 = make_float4(0.f, 0.f, 0.f, 0.f);

    for (int t = j; t < NTASK; t += WPB) {
        const float* base = h + ((size_t)(t * TASK_ROWS) * BATCH + b) * EHS;
        #pragma unroll
        for (int r = 0; r < TASK_ROWS; r += 2) {
            const float4* p0 = (const float4*)(base + (size_t)r       * row_stride);
            const float4* p1 = (const float4*)(base + (size_t)(r + 1) * row_stride);
            const float4 h00 = p0[lane], h01 = p0[lane + 32];
            const float4 h10 = p1[lane], h11 = p1[lane + 32];

            float e0 = dot4(h00, we0) + dot4(h01, we1);
            float e1 = dot4(h10, we0) + dot4(h11, we1);
            #pragma unroll
            for (int o = 16; o; o >>= 1) {
                e0 += __shfl_xor_sync(0xFFFFFFFFu, e0, o);
                e1 += __shfl_xor_sync(0xFFFFFFFFu, e1, o);
            }
            const float q0 = __expf(fmaxf(e0 + d, 0.0f));
            const float q1 = __expf(fmaxf(e1 + d, 0.0f));
            Z += q0 + q1;
            c0.x = fmaf(q0, h00.x, fmaf(q1, h10.x, c0.x));
            c0.y = fmaf(q0, h00.y, fmaf(q1, h10.y, c0.y));
            c0.z = fmaf(q0, h00.z, fmaf(q1, h10.z, c0.z));
            c0.w = fmaf(q0, h00.w, fmaf(q1, h10.w, c0.w));
            c1.x = fmaf(q0, h01.x, fmaf(q1, h11.x, c1.x));
            c1.y = fmaf(q0, h01.y, fmaf(q1, h11.y, c1.y));
            c1.z = fmaf(q0, h01.z, fmaf(q1, h11.z, c1.z));
            c1.w = fmaf(q0, h01.w, fmaf(q1, h11.w, c1.w));
        }
    }

    // plain partial store (overwritten every run -> no reset, no atomics)
    float4* dst = (float4*)(g_pc + ((size_t)j * BATCH + b) * EHS);
    dst[lane]      = c0;
    dst[lane + 32] = c1;
    if (lane == 0) g_pz[j * BATCH + b] = Z;
}

__global__ __launch_bounds__(256)
void attn_pass2(float* __restrict__ out)  // (1,64,256)
{
    const int b   = blockIdx.x;
    const int tid = threadIdx.x;

    float z = 0.0f;
    #pragma unroll 2
    for (int j = 0; j < WPB; j++) z += g_pz[j * BATCH + b];

    float c = 0.0f;
    #pragma unroll 2
    for (int j = 0; j < WPB; j++)
        c += g_pc[((size_t)j * BATCH + b) * EHS + tid];

    out[b * EHS + tid] = c / z;
}

extern "C" void kernel_launch(void* const* d_in, const int* in_sizes, int n_in,
                              void* d_out, int out_size)
{
    const float* si   = (const float*)d_in[0];  // (1,64,256)
    const float* h    = (const float*)d_in[1];  // (4096,64,256)
    const float* W    = (const float*)d_in[2];  // (1,512)
    const float* bias = (const float*)d_in[3];  // (1,)
    float* out = (float*)d_out;                 // (1,64,256)

    attn_pass1<<<NBLK, 256>>>(si, h, W, bias);
    attn_pass2<<<BATCH, 256>>>(out);
}

// round 11
// speedup vs baseline: 1.2530x; 1.2530x over previous
#include <cuda_runtime.h>
#include <math.h>

#define ESL   4096
#define BATCH 64
#define EHS   256
#define NBLK  592              // 148 SMs * 4 -> exactly 4 blocks per SM
#define WPB   74               // warp-partials per batch (592*8/64)
#define TASK_ROWS 8
#define NTASK (ESL / TASK_ROWS)  // 512 tasks per batch

// per-warp partials, batch-major: g_pc[b][j][ch], g_pz[b][j]
__device__ float g_pc[BATCH * WPB * EHS];
__device__ float g_pz[BATCH * WPB];

__device__ __forceinline__ float dot4(float4 a, float4 b) {
    return a.x*b.x + a.y*b.y + a.z*b.z + a.w*b.w;
}

__global__ __launch_bounds__(256)
void attn_pass1(const float* __restrict__ si,   // (1,64,256)
                const float* __restrict__ h,    // (4096,64,256)
                const float* __restrict__ W,    // (1,512) [Wd|We]
                const float* __restrict__ bias) // (1,)
{
    const int g    = blockIdx.x * 8 + (threadIdx.x >> 5);
    const int lane = threadIdx.x & 31;
    const int b    = g & 63;         // 4736 warps -> each b exactly 74 times
    const int j    = g >> 6;         // 0..73

    const float4* We4 = (const float4*)(W + EHS);
    const float4 we0 = We4[lane];
    const float4 we1 = We4[lane + 32];

    // d = dot(si[b], Wd) + bias
    const float4* Wd4 = (const float4*)W;
    const float4* si4 = (const float4*)(si + b * EHS);
    float4 a0 = si4[lane], a1 = si4[lane + 32];
    float4 w0 = Wd4[lane], w1 = Wd4[lane + 32];
    float d = dot4(a0, w0) + dot4(a1, w1);
    #pragma unroll
    for (int o = 16; o; o >>= 1) d += __shfl_xor_sync(0xFFFFFFFFu, d, o);
    d += bias[0];

    const size_t row_stride = (size_t)BATCH * EHS;

    float Z = 0.0f;
    float4 c0 = make_float4(0.f, 0.f, 0.f, 0.f);
    float4 c1 = make_float4(0.f, 0.f, 0.f, 0.f);

    for (int t = j; t < NTASK; t += WPB) {
        const float* base = h + ((size_t)(t * TASK_ROWS) * BATCH + b) * EHS;
        #pragma unroll
        for (int r = 0; r < TASK_ROWS; r += 2) {
            const float4* p0 = (const float4*)(base + (size_t)r       * row_stride);
            const float4* p1 = (const float4*)(base + (size_t)(r + 1) * row_stride);
            const float4 h00 = p0[lane], h01 = p0[lane + 32];
            const float4 h10 = p1[lane], h11 = p1[lane + 32];

            float e0 = dot4(h00, we0) + dot4(h01, we1);
            float e1 = dot4(h10, we0) + dot4(h11, we1);
            #pragma unroll
            for (int o = 16; o; o >>= 1) {
                e0 += __shfl_xor_sync(0xFFFFFFFFu, e0, o);
                e1 += __shfl_xor_sync(0xFFFFFFFFu, e1, o);
            }
            const float q0 = __expf(fmaxf(e0 + d, 0.0f));
            const float q1 = __expf(fmaxf(e1 + d, 0.0f));
            Z += q0 + q1;
            c0.x = fmaf(q0, h00.x, fmaf(q1, h10.x, c0.x));
            c0.y = fmaf(q0, h00.y, fmaf(q1, h10.y, c0.y));
            c0.z = fmaf(q0, h00.z, fmaf(q1, h10.z, c0.z));
            c0.w = fmaf(q0, h00.w, fmaf(q1, h10.w, c0.w));
            c1.x = fmaf(q0, h01.x, fmaf(q1, h11.x, c1.x));
            c1.y = fmaf(q0, h01.y, fmaf(q1, h11.y, c1.y));
            c1.z = fmaf(q0, h01.z, fmaf(q1, h11.z, c1.z));
            c1.w = fmaf(q0, h01.w, fmaf(q1, h11.w, c1.w));
        }
    }

    // plain partial store, batch-major layout (overwritten every run)
    float4* dst = (float4*)(g_pc + ((size_t)b * WPB + j) * EHS);
    dst[lane]      = c0;
    dst[lane + 32] = c1;
    if (lane == 0) g_pz[b * WPB + j] = Z;
}

#define P2_THREADS 1024
#define P2_GRP 16            // j-groups per block

__global__ __launch_bounds__(P2_THREADS)
void attn_pass2(float* __restrict__ out)  // (1,64,256)
{
    const int b   = blockIdx.x;
    const int tid = threadIdx.x;
    const int ch4 = tid & 63;     // float4 channel index (0..63)
    const int grp = tid >> 6;     // j-group (0..15)

    // ---- context partial sum: j = grp, grp+16, ... ----
    const float4* base = (const float4*)(g_pc + (size_t)b * WPB * EHS);
    float4 c = make_float4(0.f, 0.f, 0.f, 0.f);
    for (int j = grp; j < WPB; j += P2_GRP) {
        float4 v = base[j * (EHS / 4) + ch4];
        c.x += v.x; c.y += v.y; c.z += v.z; c.w += v.w;
    }

    __shared__ __align__(16) float4 s_c[P2_GRP][EHS / 4];   // 16 KB
    __shared__ float s_zp[128];
    __shared__ float s_z;
    s_c[grp][ch4] = c;

    // ---- Z reduce ----
    s_zp[tid & 127] = 0.0f;   // (first 128 threads' writes suffice; all write same pattern)
    __syncthreads();
    if (tid < WPB) s_zp[tid] = g_pz[b * WPB + tid];
    __syncthreads();
    if (tid < 32) {
        float z = s_zp[tid] + s_zp[tid + 32] + s_zp[tid + 64] + s_zp[tid + 96];
        #pragma unroll
        for (int o = 16; o; o >>= 1) z += __shfl_xor_sync(0xFFFFFFFFu, z, o);
        if (tid == 0) s_z = z;
    }
    __syncthreads();

    // ---- final combine + normalize ----
    if (tid < 64) {
        float4 t = s_c[0][tid];
        #pragma unroll
        for (int gq = 1; gq < P2_GRP; gq++) {
            float4 u = s_c[gq][tid];
            t.x += u.x; t.y += u.y; t.z += u.z; t.w += u.w;
        }
        const float inv = 1.0f / s_z;
        t.x *= inv; t.y *= inv; t.z *= inv; t.w *= inv;
        ((float4*)(out + b * EHS))[tid] = t;
    }
}

extern "C" void kernel_launch(void* const* d_in, const int* in_sizes, int n_in,
                              void* d_out, int out_size)
{
    const float* si   = (const float*)d_in[0];  // (1,64,256)
    const float* h    = (const float*)d_in[1];  // (4096,64,256)
    const float* W    = (const float*)d_in[2];  // (1,512)
    const float* bias = (const float*)d_in[3];  // (1,)
    float* out = (float*)d_out;                 // (1,64,256)

    attn_pass1<<<NBLK, 256>>>(si, h, W, bias);
    attn_pass2<<<BATCH, P2_THREADS>>>(out);
}

// round 12
// speedup vs baseline: 1.3841x; 1.1046x over previous
#include <cuda_runtime.h>
#include <math.h>

#define ESL    4096
#define BATCH  64
#define EHS    256
#define SLICES 9
#define NBLK   (BATCH * SLICES)   // 576 blocks = one wave at 4 blocks/SM
#define TASK_ROWS 8
#define NTASK  (ESL / TASK_ROWS)  // 512 tasks of 8 rows

// block-level partials: g_pc[b][slice][ch], g_pz[b][slice]  (589 KB -> L2-resident)
__device__ float g_pc[BATCH * SLICES * EHS];
__device__ float g_pz[BATCH * SLICES];

__device__ __forceinline__ float dot4(float4 a, float4 b) {
    return a.x*b.x + a.y*b.y + a.z*b.z + a.w*b.w;
}

__global__ __launch_bounds__(256)
void attn_pass1(const float* __restrict__ si,   // (1,64,256)
                const float* __restrict__ h,    // (4096,64,256)
                const float* __restrict__ W,    // (1,512) [Wd|We]
                const float* __restrict__ bias) // (1,)
{
    const int b     = blockIdx.x % BATCH;
    const int slice = blockIdx.x / BATCH;       // 0..8
    const int tid   = threadIdx.x;
    const int w     = tid >> 5;
    const int lane  = tid & 31;

    // We slices for this lane (channels 4*lane and 4*(lane+32))
    const float4* We4 = (const float4*)(W + EHS);
    const float4 we0 = We4[lane];
    const float4 we1 = We4[lane + 32];

    // d = dot(si[b], Wd) + bias (redundant per warp; negligible)
    const float4* Wd4 = (const float4*)W;
    const float4* si4 = (const float4*)(si + b * EHS);
    float4 a0 = si4[lane], a1 = si4[lane + 32];
    float4 w0 = Wd4[lane], w1 = Wd4[lane + 32];
    float d = dot4(a0, w0) + dot4(a1, w1);
    #pragma unroll
    for (int o = 16; o; o >>= 1) d += __shfl_xor_sync(0xFFFFFFFFu, d, o);
    d += bias[0];

    const size_t row_stride = (size_t)BATCH * EHS;  // floats between s and s+1
    const float* hb = h + (size_t)b * EHS;

    float Z = 0.0f;
    float4 c0 = make_float4(0.f, 0.f, 0.f, 0.f);
    float4 c1 = make_float4(0.f, 0.f, 0.f, 0.f);

    // process one row per warp per task; two tasks in flight for MLP
    int t = slice;
    for (; t + SLICES < NTASK; t += 2 * SLICES) {
        const int s0 = t * TASK_ROWS + w;
        const int s1 = (t + SLICES) * TASK_ROWS + w;
        const float4* p0 = (const float4*)(hb + (size_t)s0 * row_stride);
        const float4* p1 = (const float4*)(hb + (size_t)s1 * row_stride);
        const float4 h00 = p0[lane], h01 = p0[lane + 32];
        const float4 h10 = p1[lane], h11 = p1[lane + 32];

        float e0 = dot4(h00, we0) + dot4(h01, we1);
        float e1 = dot4(h10, we0) + dot4(h11, we1);
        #pragma unroll
        for (int o = 16; o; o >>= 1) {
            e0 += __shfl_xor_sync(0xFFFFFFFFu, e0, o);
            e1 += __shfl_xor_sync(0xFFFFFFFFu, e1, o);
        }
        const float q0 = __expf(fmaxf(e0 + d, 0.0f));
        const float q1 = __expf(fmaxf(e1 + d, 0.0f));
        Z += q0 + q1;
        c0.x = fmaf(q0, h00.x, fmaf(q1, h10.x, c0.x));
        c0.y = fmaf(q0, h00.y, fmaf(q1, h10.y, c0.y));
        c0.z = fmaf(q0, h00.z, fmaf(q1, h10.z, c0.z));
        c0.w = fmaf(q0, h00.w, fmaf(q1, h10.w, c0.w));
        c1.x = fmaf(q0, h01.x, fmaf(q1, h11.x, c1.x));
        c1.y = fmaf(q0, h01.y, fmaf(q1, h11.y, c1.y));
        c1.z = fmaf(q0, h01.z, fmaf(q1, h11.z, c1.z));
        c1.w = fmaf(q0, h01.w, fmaf(q1, h11.w, c1.w));
    }
    if (t < NTASK) {   // leftover single task
        const int s0 = t * TASK_ROWS + w;
        const float4* p0 = (const float4*)(hb + (size_t)s0 * row_stride);
        const float4 h00 = p0[lane], h01 = p0[lane + 32];
        float e0 = dot4(h00, we0) + dot4(h01, we1);
        #pragma unroll
        for (int o = 16; o; o >>= 1) e0 += __shfl_xor_sync(0xFFFFFFFFu, e0, o);
        const float q0 = __expf(fmaxf(e0 + d, 0.0f));
        Z += q0;
        c0.x = fmaf(q0, h00.x, c0.x); c0.y = fmaf(q0, h00.y, c0.y);
        c0.z = fmaf(q0, h00.z, c0.z); c0.w = fmaf(q0, h00.w, c0.w);
        c1.x = fmaf(q0, h01.x, c1.x); c1.y = fmaf(q0, h01.y, c1.y);
        c1.z = fmaf(q0, h01.z, c1.z); c1.w = fmaf(q0, h01.w, c1.w);
    }

    // ---- block combine: 8 warps -> 1 partial ----
    __shared__ __align__(16) float4 s_c4[8][EHS / 4];   // 8 KB
    __shared__ float s_z[8];
    s_c4[w][lane]      = c0;
    s_c4[w][lane + 32] = c1;
    if (lane == 0) s_z[w] = Z;
    __syncthreads();

    if (tid < 64) {
        float4 acc = s_c4[0][tid];
        #pragma unroll
        for (int p = 1; p < 8; p++) {
            float4 u = s_c4[p][tid];
            acc.x += u.x; acc.y += u.y; acc.z += u.z; acc.w += u.w;
        }
        ((float4*)(g_pc + ((size_t)b * SLICES + slice) * EHS))[tid] = acc;
    }
    if (tid == 0) {
        float zt = 0.0f;
        #pragma unroll
        for (int p = 0; p < 8; p++) zt += s_z[p];
        g_pz[b * SLICES + slice] = zt;
    }
}

__global__ __launch_bounds__(256)
void attn_pass2(float* __restrict__ out)  // (1,64,256)
{
    const int b   = blockIdx.x;
    const int tid = threadIdx.x;

    float z = 0.0f;
    #pragma unroll
    for (int s = 0; s < SLICES; s++) z += g_pz[b * SLICES + s];

    float c = 0.0f;
    #pragma unroll
    for (int s = 0; s < SLICES; s++)
        c += g_pc[((size_t)b * SLICES + s) * EHS + tid];

    out[b * EHS + tid] = c / z;
}

extern "C" void kernel_launch(void* const* d_in, const int* in_sizes, int n_in,
                              void* d_out, int out_size)
{
    const float* si   = (const float*)d_in[0];  // (1,64,256)
    const float* h    = (const float*)d_in[1];  // (4096,64,256)
    const float* W    = (const float*)d_in[2];  // (1,512)
    const float* bias = (const float*)d_in[3];  // (1,)
    float* out = (float*)d_out;                 // (1,64,256)

    attn_pass1<<<NBLK, 256>>>(si, h, W, bias);
    attn_pass2<<<BATCH, 256>>>(out);
}

// round 13
// speedup vs baseline: 1.4016x; 1.0126x over previous
#include <cuda_runtime.h>
#include <math.h>

#define ESL    4096
#define BATCH  64
#define EHS    256
#define SLICES 9
#define NBLK   (BATCH * SLICES)   // 576 blocks ~= one wave at 4 blocks/SM
#define TASK_ROWS 8
#define NTASK  (ESL / TASK_ROWS)  // 512 tasks of 8 rows

// block-level partials: g_pc[b][slice][ch], g_pz[b][slice]  (589 KB -> L2-hot)
__device__ float g_pc[BATCH * SLICES * EHS];
__device__ float g_pz[BATCH * SLICES];
__device__ int   g_cnt[BATCH];    // zero-init; consumer resets each run

__device__ __forceinline__ float dot4(float4 a, float4 b) {
    return a.x*b.x + a.y*b.y + a.z*b.z + a.w*b.w;
}

__global__ __launch_bounds__(256)
void attn_fused(const float* __restrict__ si,   // (1,64,256)
                const float* __restrict__ h,    // (4096,64,256)
                const float* __restrict__ W,    // (1,512) [Wd|We]
                const float* __restrict__ bias, // (1,)
                float* __restrict__ out)        // (1,64,256)
{
    const int b     = blockIdx.x % BATCH;
    const int slice = blockIdx.x / BATCH;       // 0..8
    const int tid   = threadIdx.x;
    const int w     = tid >> 5;
    const int lane  = tid & 31;

    const float4* We4 = (const float4*)(W + EHS);
    const float4 we0 = We4[lane];
    const float4 we1 = We4[lane + 32];

    // d = dot(si[b], Wd) + bias
    const float4* Wd4 = (const float4*)W;
    const float4* si4 = (const float4*)(si + b * EHS);
    float4 a0 = si4[lane], a1 = si4[lane + 32];
    float4 w0 = Wd4[lane], w1 = Wd4[lane + 32];
    float d = dot4(a0, w0) + dot4(a1, w1);
    #pragma unroll
    for (int o = 16; o; o >>= 1) d += __shfl_xor_sync(0xFFFFFFFFu, d, o);
    d += bias[0];

    const size_t row_stride = (size_t)BATCH * EHS;
    const float* hb = h + (size_t)b * EHS;

    float Z = 0.0f;
    float4 c0 = make_float4(0.f, 0.f, 0.f, 0.f);
    float4 c1 = make_float4(0.f, 0.f, 0.f, 0.f);

    // one row per warp per task; two tasks in flight for MLP
    int t = slice;
    for (; t + SLICES < NTASK; t += 2 * SLICES) {
        const int s0 = t * TASK_ROWS + w;
        const int s1 = (t + SLICES) * TASK_ROWS + w;
        const float4* p0 = (const float4*)(hb + (size_t)s0 * row_stride);
        const float4* p1 = (const float4*)(hb + (size_t)s1 * row_stride);
        const float4 h00 = p0[lane], h01 = p0[lane + 32];
        const float4 h10 = p1[lane], h11 = p1[lane + 32];

        float e0 = dot4(h00, we0) + dot4(h01, we1);
        float e1 = dot4(h10, we0) + dot4(h11, we1);
        #pragma unroll
        for (int o = 16; o; o >>= 1) {
            e0 += __shfl_xor_sync(0xFFFFFFFFu, e0, o);
            e1 += __shfl_xor_sync(0xFFFFFFFFu, e1, o);
        }
        const float q0 = __expf(fmaxf(e0 + d, 0.0f));
        const float q1 = __expf(fmaxf(e1 + d, 0.0f));
        Z += q0 + q1;
        c0.x = fmaf(q0, h00.x, fmaf(q1, h10.x, c0.x));
        c0.y = fmaf(q0, h00.y, fmaf(q1, h10.y, c0.y));
        c0.z = fmaf(q0, h00.z, fmaf(q1, h10.z, c0.z));
        c0.w = fmaf(q0, h00.w, fmaf(q1, h10.w, c0.w));
        c1.x = fmaf(q0, h01.x, fmaf(q1, h11.x, c1.x));
        c1.y = fmaf(q0, h01.y, fmaf(q1, h11.y, c1.y));
        c1.z = fmaf(q0, h01.z, fmaf(q1, h11.z, c1.z));
        c1.w = fmaf(q0, h01.w, fmaf(q1, h11.w, c1.w));
    }
    if (t < NTASK) {   // leftover single task
        const int s0 = t * TASK_ROWS + w;
        const float4* p0 = (const float4*)(hb + (size_t)s0 * row_stride);
        const float4 h00 = p0[lane], h01 = p0[lane + 32];
        float e0 = dot4(h00, we0) + dot4(h01, we1);
        #pragma unroll
        for (int o = 16; o; o >>= 1) e0 += __shfl_xor_sync(0xFFFFFFFFu, e0, o);
        const float q0 = __expf(fmaxf(e0 + d, 0.0f));
        Z += q0;
        c0.x = fmaf(q0, h00.x, c0.x); c0.y = fmaf(q0, h00.y, c0.y);
        c0.z = fmaf(q0, h00.z, c0.z); c0.w = fmaf(q0, h00.w, c0.w);
        c1.x = fmaf(q0, h01.x, c1.x); c1.y = fmaf(q0, h01.y, c1.y);
        c1.z = fmaf(q0, h01.z, c1.z); c1.w = fmaf(q0, h01.w, c1.w);
    }

    // ---- block combine: 8 warps -> 1 partial ----
    __shared__ __align__(16) float4 s_c4[8][EHS / 4];   // 8 KB
    __shared__ float s_z[8];
    __shared__ bool  s_last;
    s_c4[w][lane]      = c0;
    s_c4[w][lane + 32] = c1;
    if (lane == 0) s_z[w] = Z;
    __syncthreads();

    if (tid < 64) {
        float4 acc = s_c4[0][tid];
        #pragma unroll
        for (int p = 1; p < 8; p++) {
            float4 u = s_c4[p][tid];
            acc.x += u.x; acc.y += u.y; acc.z += u.z; acc.w += u.w;
        }
        ((float4*)(g_pc + ((size_t)b * SLICES + slice) * EHS))[tid] = acc;
    }
    if (tid == 0) {
        float zt = 0.0f;
        #pragma unroll
        for (int p = 0; p < 8; p++) zt += s_z[p];
        g_pz[b * SLICES + slice] = zt;
    }

    // ---- fused tail: last block per batch reduces its 9 partials ----
    __threadfence();
    __syncthreads();
    if (tid == 0) s_last = (atomicAdd(&g_cnt[b], 1) == SLICES - 1);
    __syncthreads();
    if (s_last) {
        __threadfence();   // acquire: all 9 partials visible
        float z = 0.0f;
        #pragma unroll
        for (int s = 0; s < SLICES; s++) z += g_pz[b * SLICES + s];
        float c = 0.0f;
        #pragma unroll
        for (int s = 0; s < SLICES; s++)
            c += g_pc[((size_t)b * SLICES + s) * EHS + tid];
        out[b * EHS + tid] = c / z;
        if (tid == 0) g_cnt[b] = 0;   // reset for next graph replay
    }
}

extern "C" void kernel_launch(void* const* d_in, const int* in_sizes, int n_in,
                              void* d_out, int out_size)
{
    const float* si   = (const float*)d_in[0];  // (1,64,256)
    const float* h    = (const float*)d_in[1];  // (4096,64,256)
    const float* W    = (const float*)d_in[2];  // (1,512)
    const float* bias = (const float*)d_in[3];  // (1,)
    float* out = (float*)d_out;                 // (1,64,256)

    attn_fused<<<NBLK, 256>>>(si, h, W, bias, out);
}

// round 14
// speedup vs baseline: 1.5561x; 1.1103x over previous
#include <cuda_runtime.h>
#include <math.h>

#define ESL    4096
#define BATCH  64
#define EHS    256
#define SLICES 9
#define NBLK   (BATCH * SLICES)   // 576 blocks ~= one wave at 4 blocks/SM
#define STRIDE 72                 // 72 warp-streams per batch (9 slices * 8 warps)

// block-level partials: g_pc[b][slice][ch], g_pz[b][slice]  (589 KB -> L2-hot)
__device__ float g_pc[BATCH * SLICES * EHS];
__device__ float g_pz[BATCH * SLICES];
__device__ int   g_cnt[BATCH];    // zero-init; consumer resets each run

__device__ __forceinline__ float dot4(float4 a, float4 b) {
    return a.x*b.x + a.y*b.y + a.z*b.z + a.w*b.w;
}

__global__ __launch_bounds__(256, 4)
void attn_fused(const float* __restrict__ si,   // (1,64,256)
                const float* __restrict__ h,    // (4096,64,256)
                const float* __restrict__ W,    // (1,512) [Wd|We]
                const float* __restrict__ bias, // (1,)
                float* __restrict__ out)        // (1,64,256)
{
    const int b     = blockIdx.x & 63;
    const int slice = blockIdx.x >> 6;          // 0..8
    const int tid   = threadIdx.x;
    const int w     = tid >> 5;
    const int lane  = tid & 31;

    const float4* We4 = (const float4*)(W + EHS);
    const float4 we0 = We4[lane];
    const float4 we1 = We4[lane + 32];

    // d = dot(si[b], Wd) + bias
    const float4* Wd4 = (const float4*)W;
    const float4* si4 = (const float4*)(si + b * EHS);
    float4 a0 = si4[lane], a1 = si4[lane + 32];
    float4 w0 = Wd4[lane], w1 = Wd4[lane + 32];
    float d = dot4(a0, w0) + dot4(a1, w1);
    #pragma unroll
    for (int o = 16; o; o >>= 1) d += __shfl_xor_sync(0xFFFFFFFFu, d, o);
    d += bias[0];

    const size_t rs = (size_t)BATCH * EHS;      // floats between s and s+1
    const float* hb = h + (size_t)b * EHS;

    // warp-stream: rows s = j, j+72, j+144, ...  (every warp has >= 56 rows)
    const int j = slice * 8 + w;                // 0..71

    float Z = 0.0f;
    float4 c0 = make_float4(0.f, 0.f, 0.f, 0.f);
    float4 c1 = make_float4(0.f, 0.f, 0.f, 0.f);

    // 2-deep register prefetch pipeline
    const float4* p0 = (const float4*)(hb + (size_t)j * rs);
    float4 f0 = p0[lane], f1 = p0[lane + 32];            // row j
    const float4* p1 = (const float4*)(hb + (size_t)(j + STRIDE) * rs);
    float4 g0 = p1[lane], g1 = p1[lane + 32];            // row j+72

    for (int s = j; s < ESL; s += STRIDE) {
        const float4 u0 = f0, u1 = f1;                   // row s (consume)
        f0 = g0; f1 = g1;                                // shift pipeline
        const int sn = s + 2 * STRIDE;
        if (sn < ESL) {                                  // prefetch row s+144
            const float4* pn = (const float4*)(hb + (size_t)sn * rs);
            g0 = pn[lane]; g1 = pn[lane + 32];
        }

        float e = dot4(u0, we0) + dot4(u1, we1);
        #pragma unroll
        for (int o = 16; o; o >>= 1) e += __shfl_xor_sync(0xFFFFFFFFu, e, o);
        const float q = __expf(fmaxf(e + d, 0.0f));
        Z += q;
        c0.x = fmaf(q, u0.x, c0.x); c0.y = fmaf(q, u0.y, c0.y);
        c0.z = fmaf(q, u0.z, c0.z); c0.w = fmaf(q, u0.w, c0.w);
        c1.x = fmaf(q, u1.x, c1.x); c1.y = fmaf(q, u1.y, c1.y);
        c1.z = fmaf(q, u1.z, c1.z); c1.w = fmaf(q, u1.w, c1.w);
    }

    // ---- block combine: 8 warps -> 1 partial ----
    __shared__ __align__(16) float4 s_c4[8][EHS / 4];   // 8 KB
    __shared__ float s_z[8];
    __shared__ bool  s_last;
    s_c4[w][lane]      = c0;
    s_c4[w][lane + 32] = c1;
    if (lane == 0) s_z[w] = Z;
    __syncthreads();

    if (tid < 64) {
        float4 acc = s_c4[0][tid];
        #pragma unroll
        for (int p = 1; p < 8; p++) {
            float4 u = s_c4[p][tid];
            acc.x += u.x; acc.y += u.y; acc.z += u.z; acc.w += u.w;
        }
        ((float4*)(g_pc + ((size_t)b * SLICES + slice) * EHS))[tid] = acc;
    }
    if (tid == 0) {
        float zt = 0.0f;
        #pragma unroll
        for (int p = 0; p < 8; p++) zt += s_z[p];
        g_pz[b * SLICES + slice] = zt;
    }

    // ---- fused tail: last block per batch reduces its 9 partials ----
    __threadfence();
    __syncthreads();
    if (tid == 0) s_last = (atomicAdd(&g_cnt[b], 1) == SLICES - 1);
    __syncthreads();
    if (s_last) {
        __threadfence();   // acquire: all 9 partials visible
        float z = 0.0f;
        #pragma unroll
        for (int s = 0; s < SLICES; s++) z += g_pz[b * SLICES + s];
        float c = 0.0f;
        #pragma unroll
        for (int s = 0; s < SLICES; s++)
            c += g_pc[((size_t)b * SLICES + s) * EHS + tid];
        out[b * EHS + tid] = c / z;
        if (tid == 0) g_cnt[b] = 0;   // reset for next graph replay
    }
}

extern "C" void kernel_launch(void* const* d_in, const int* in_sizes, int n_in,
                              void* d_out, int out_size)
{
    const float* si   = (const float*)d_in[0];  // (1,64,256)
    const float* h    = (const float*)d_in[1];  // (4096,64,256)
    const float* W    = (const float*)d_in[2];  // (1,512)
    const float* bias = (const float*)d_in[3];  // (1,)
    float* out = (float*)d_out;                 // (1,64,256)

    attn_fused<<<NBLK, 256>>>(si, h, W, bias, out);
}